// round 1
// baseline (speedup 1.0000x reference)
#include <cuda_runtime.h>
#include <math.h>

#define Bn 4
#define Tn 2048
#define Dn 1024
#define Hn 4
#define Mn 64
#define HK 128
#define HV 256

// ---------------- scratch (static __device__ globals; no allocation) -------
__device__ float bufQP[Bn*Tn*512];
__device__ float bufKP[Bn*Tn*512];
__device__ float bufVP[Bn*Tn*1024];
__device__ float bufQC[Bn*Tn*512];
__device__ float bufKC[Bn*Tn*512];
__device__ float bufVC[Bn*Tn*1024];
__device__ float bufS [Bn*Tn*256];
__device__ float bufGP[Bn*Tn*1024];
__device__ float bufQV[Bn*Tn*256];
__device__ float bufG [Bn*Tn*256];
__device__ float bufSN[Bn*Tn*256];
__device__ float bufOV[Bn*Tn*1024];
__device__ float bufOF[Bn*Tn*1024];

// ---------------- SGEMM: C[M,N] = A[M,K] @ B[K,N], all row-major, fp32 -----
// 128x128 tile, BK=16, 256 threads, 8x8 per thread.
__global__ void __launch_bounds__(256) sgemm128(
    const float* __restrict__ A, const float* __restrict__ B,
    float* __restrict__ C, int Mr, int Nr, int Kr)
{
    __shared__ __align__(16) float As[16][132];
    __shared__ __align__(16) float Bs[16][132];
    int tid = threadIdx.x;
    int tx = tid & 15, ty = tid >> 4;
    int row0 = blockIdx.y * 128, col0 = blockIdx.x * 128;
    float acc[8][8];
#pragma unroll
    for (int i = 0; i < 8; i++)
#pragma unroll
        for (int j = 0; j < 8; j++) acc[i][j] = 0.f;

    const float* Aptr = A + (long)row0 * Kr;
    for (int k0 = 0; k0 < Kr; k0 += 16) {
#pragma unroll
        for (int l = 0; l < 8; l++) {
            int lid = tid + l * 256;
            int r = lid >> 4, cc = lid & 15;           // A tile 128x16
            As[cc][r] = Aptr[(long)r * Kr + k0 + cc];
        }
#pragma unroll
        for (int l = 0; l < 8; l++) {
            int lid = tid + l * 256;
            int r = lid >> 7, cc = lid & 127;          // B tile 16x128
            Bs[r][cc] = B[(long)(k0 + r) * Nr + col0 + cc];
        }
        __syncthreads();
#pragma unroll
        for (int kk = 0; kk < 16; kk++) {
            float a[8], b[8];
            *(float4*)&a[0] = *(const float4*)&As[kk][ty * 8];
            *(float4*)&a[4] = *(const float4*)&As[kk][ty * 8 + 4];
            *(float4*)&b[0] = *(const float4*)&Bs[kk][tx * 8];
            *(float4*)&b[4] = *(const float4*)&Bs[kk][tx * 8 + 4];
#pragma unroll
            for (int i = 0; i < 8; i++)
#pragma unroll
                for (int j = 0; j < 8; j++)
                    acc[i][j] = fmaf(a[i], b[j], acc[i][j]);
        }
        __syncthreads();
    }
#pragma unroll
    for (int i = 0; i < 8; i++) {
        long r = row0 + ty * 8 + i;
#pragma unroll
        for (int j = 0; j < 8; j++)
            C[r * Nr + col0 + tx * 8 + j] = acc[i][j];
    }
}

// ---------------- depthwise causal conv1d (KS=4) + SiLU --------------------
__global__ void conv_silu(const float* __restrict__ x, const float* __restrict__ w,
                          float* __restrict__ y, int C)
{
    long idx = (long)blockIdx.x * blockDim.x + threadIdx.x;
    long total = (long)Bn * Tn * C;
    if (idx >= total) return;
    int cidx = idx % C;
    long bt = idx / C;
    int tt = (int)(bt % Tn);
    long bb = bt / Tn;
    float acc = 0.f;
#pragma unroll
    for (int j = 0; j < 4; j++) {
        int ts = tt - 3 + j;
        if (ts >= 0)
            acc = fmaf(x[(bb * Tn + ts) * C + cidx], w[cidx * 4 + j], acc);
    }
    y[idx] = acc / (1.f + expf(-acc));
}

// ---------------- RoPE (in-place, paired halves) ---------------------------
__global__ void rope_kernel(float* __restrict__ q, float* __restrict__ k)
{
    long idx = (long)blockIdx.x * blockDim.x + threadIdx.x;
    long total = (long)Bn * Tn * 512 / 2;  // pairs
    if (idx >= total) return;
    int j = idx & 63;
    long rest = idx >> 6;
    int hh = (int)(rest & 3);
    long bt = rest >> 2;
    int tt = (int)(bt % Tn);
    long base = bt * 512 + hh * 128;
    float inv = expf(-(float)(2 * j) * (9.210340371976184f / 128.0f));
    float fr = (float)tt * inv;
    float cs = cosf(fr), sn = sinf(fr);
    float q1 = q[base + j], q2 = q[base + j + 64];
    float k1 = k[base + j], k2 = k[base + j + 64];
    q[base + j]      = q1 * cs - q2 * sn;
    q[base + j + 64] = q2 * cs + q1 * sn;
    k[base + j]      = k1 * cs - k2 * sn;
    k[base + j + 64] = k2 * cs + k1 * sn;
}

// ---------------- scan phase 1: z-scan, hk state, ok, softmax -> qv --------
// grid 16 = (b,h); 512 threads; thread owns 16 hk elems: m = t>>3, k-seg = t&7
__global__ void __launch_bounds__(512) scan_phase1(
    const float* __restrict__ qc, const float* __restrict__ kc,
    const float* __restrict__ sraw,
    float* __restrict__ qv, float* __restrict__ gbuf, float* __restrict__ snbuf)
{
    int bh = blockIdx.x;
    int b = bh >> 2, h = bh & 3;
    int t = threadIdx.x;
    int m1 = t >> 3, kseg = t & 7, kb = kseg * 16;
    __shared__ float zprev[64], g_s[64], sn_s[64];
    __shared__ float qsm[128], ksm[128], oksm[64];
    float hk[16];
#pragma unroll
    for (int i = 0; i < 16; i++) hk[i] = 0.f;
    if (t < 64) zprev[t] = -INFINITY;
    __syncthreads();
    const float scale = 0.08838834764831845f;  // 1/sqrt(128)

    for (int step = 0; step < Tn; step++) {
        long base_qk = ((long)b * Tn + step) * 512 + h * 128;
        if (t < 64) {
            float sv = sraw[((long)b * Tn + step) * 256 + h * 64 + t];
            sv = fminf(32.f, fmaxf(-32.f, sv));
            float zp = zprev[t];
            float z, g;
            if (zp == -INFINITY) { z = sv; g = 0.f; }
            else {
                float mx = fmaxf(zp, sv);
                z = mx + log1pf(expf(fminf(zp, sv) - mx));
                g = expf(zp - z);
            }
            float sn = expf(sv - z);
            zprev[t] = z; g_s[t] = g; sn_s[t] = sn;
            long gi = ((long)b * Tn + step) * 256 + h * 64 + t;
            gbuf[gi] = g; snbuf[gi] = sn;
        } else if (t < 192) {
            int i = t - 64;
            qsm[i] = qc[base_qk + i] * scale;
        } else if (t < 320) {
            int i = t - 192;
            ksm[i] = kc[base_qk + i];
        }
        __syncthreads();

        float gm = g_s[m1], snm = sn_s[m1];
        float acc = 0.f;
#pragma unroll
        for (int i = 0; i < 16; i++) {
            float hkv = fmaf(hk[i], gm, ksm[kb + i] * snm);
            hk[i] = hkv;
            acc = fmaf(qsm[kb + i], hkv, acc);
        }
        acc += __shfl_xor_sync(0xffffffffu, acc, 4);
        acc += __shfl_xor_sync(0xffffffffu, acc, 2);
        acc += __shfl_xor_sync(0xffffffffu, acc, 1);
        if (kseg == 0) oksm[m1] = acc;
        __syncthreads();

        if (t < 32) {
            float v0 = oksm[t], v1 = oksm[t + 32];
            float mx = fmaxf(v0, v1);
#pragma unroll
            for (int off = 16; off; off >>= 1)
                mx = fmaxf(mx, __shfl_xor_sync(0xffffffffu, mx, off));
            float e0 = expf(v0 - mx), e1 = expf(v1 - mx);
            float sum = e0 + e1;
#pragma unroll
            for (int off = 16; off; off >>= 1)
                sum += __shfl_xor_sync(0xffffffffu, sum, off);
            float invs = 1.f / sum;
            long qi = ((long)b * Tn + step) * 256 + h * 64 + t;
            qv[qi] = e0 * invs; qv[qi + 32] = e1 * invs;
        }
        // second barrier of the step is next iteration's first __syncthreads:
        // writes to g_s/qsm/ksm next iter happen after this iteration's
        // mid-barrier readers finished (they passed the oksm barrier).
    }
}

// ---------------- scan phase 2: hv state, ov -------------------------------
// grid 64 = (b,h,vchunk of 64); 256 threads; thread owns 16 hv elems:
// v = t>>2 within chunk, m-quarter = t&3
__global__ void __launch_bounds__(256) scan_phase2(
    const float* __restrict__ qv, const float* __restrict__ gbuf,
    const float* __restrict__ snbuf, const float* __restrict__ vc,
    float* __restrict__ ov)
{
    int blk = blockIdx.x;
    int c = blk & 3, h = (blk >> 2) & 3, b = blk >> 4;
    int t = threadIdx.x;
    int vloc = t >> 2;
    int q4 = t & 3, mb = q4 * 16;
    int vcol = h * 256 + c * 64 + vloc;
    __shared__ float g_s[64], sn_s[64], qv_s[64];
    float hv[16];
#pragma unroll
    for (int i = 0; i < 16; i++) hv[i] = 0.f;

    for (int step = 0; step < Tn; step++) {
        long gi = ((long)b * Tn + step) * 256 + h * 64;
        float vval = vc[((long)b * Tn + step) * 1024 + vcol];
        if (t < 64) {
            g_s[t]  = gbuf[gi + t];
            sn_s[t] = snbuf[gi + t];
            qv_s[t] = qv[gi + t];
        }
        __syncthreads();
        float acc = 0.f;
#pragma unroll
        for (int i = 0; i < 16; i++) {
            int m = mb + i;
            float hvv = fmaf(hv[i], g_s[m], sn_s[m] * vval);
            hv[i] = hvv;
            acc = fmaf(qv_s[m], hvv, acc);
        }
        acc += __shfl_xor_sync(0xffffffffu, acc, 1);
        acc += __shfl_xor_sync(0xffffffffu, acc, 2);
        if (q4 == 0) ov[((long)b * Tn + step) * 1024 + vcol] = acc;
        __syncthreads();
    }
}

// ---------------- RMS-ish norm over head dim + SiLU gate -------------------
__global__ void normgate(const float* __restrict__ ovb, const float* __restrict__ gp,
                         const float* __restrict__ gw, float* __restrict__ out)
{
    int warp = (int)(((long)blockIdx.x * blockDim.x + threadIdx.x) >> 5);
    int lane = threadIdx.x & 31;
    if (warp >= Bn * Tn * Hn) return;
    long base = (long)warp * 256;   // [B,T,H,256] contiguous
    float vals[8];
    float ss = 0.f;
#pragma unroll
    for (int i = 0; i < 8; i++) {
        float v = ovb[base + lane + i * 32];
        vals[i] = v;
        ss = fmaf(v, v, ss);
    }
#pragma unroll
    for (int off = 16; off; off >>= 1)
        ss += __shfl_xor_sync(0xffffffffu, ss, off);
    float scale = rsqrtf(ss * (1.f / 256.f) + 1e-5f);
#pragma unroll
    for (int i = 0; i < 8; i++) {
        int j = lane + i * 32;
        float gv = gp[base + j];
        float sil = gv / (1.f + expf(-gv));
        out[base + j] = vals[i] * scale * gw[j] * sil;
    }
}

// ---------------- host launch ----------------------------------------------
extern "C" void kernel_launch(void* const* d_in, const int* in_sizes, int n_in,
                              void* d_out, int out_size)
{
    const float* X  = (const float*)d_in[0];
    const float* Wq = (const float*)d_in[1];
    const float* Wk = (const float*)d_in[2];
    const float* Wv = (const float*)d_in[3];
    const float* Ws = (const float*)d_in[4];
    const float* Wg = (const float*)d_in[5];
    const float* Wo = (const float*)d_in[6];
    const float* qw = (const float*)d_in[7];
    const float* kw = (const float*)d_in[8];
    const float* vw = (const float*)d_in[9];
    const float* gw = (const float*)d_in[10];
    float* out = (float*)d_out;

    float *qp, *kp, *vp, *qc, *kc, *vc, *sb, *gp, *qv, *gb, *sn, *ovb, *of;
    cudaGetSymbolAddress((void**)&qp, bufQP);
    cudaGetSymbolAddress((void**)&kp, bufKP);
    cudaGetSymbolAddress((void**)&vp, bufVP);
    cudaGetSymbolAddress((void**)&qc, bufQC);
    cudaGetSymbolAddress((void**)&kc, bufKC);
    cudaGetSymbolAddress((void**)&vc, bufVC);
    cudaGetSymbolAddress((void**)&sb, bufS);
    cudaGetSymbolAddress((void**)&gp, bufGP);
    cudaGetSymbolAddress((void**)&qv, bufQV);
    cudaGetSymbolAddress((void**)&gb, bufG);
    cudaGetSymbolAddress((void**)&sn, bufSN);
    cudaGetSymbolAddress((void**)&ovb, bufOV);
    cudaGetSymbolAddress((void**)&of, bufOF);

    const int Mr = Bn * Tn;  // 8192

    // projections
    sgemm128<<<dim3(512 / 128, Mr / 128), 256>>>(X, Wq, qp, Mr, 512, 1024);
    sgemm128<<<dim3(512 / 128, Mr / 128), 256>>>(X, Wk, kp, Mr, 512, 1024);
    sgemm128<<<dim3(1024 / 128, Mr / 128), 256>>>(X, Wv, vp, Mr, 1024, 1024);
    sgemm128<<<dim3(256 / 128, Mr / 128), 256>>>(X, Ws, sb, Mr, 256, 1024);
    sgemm128<<<dim3(1024 / 128, Mr / 128), 256>>>(X, Wg, gp, Mr, 1024, 1024);

    // conv + silu
    conv_silu<<<(Bn * Tn * 512 + 255) / 256, 256>>>(qp, qw, qc, 512);
    conv_silu<<<(Bn * Tn * 512 + 255) / 256, 256>>>(kp, kw, kc, 512);
    conv_silu<<<(Bn * Tn * 1024 + 255) / 256, 256>>>(vp, vw, vc, 1024);

    // rope (in-place on qc, kc)
    rope_kernel<<<(Bn * Tn * 512 / 2 + 255) / 256, 256>>>(qc, kc);

    // sequential scans
    scan_phase1<<<Bn * Hn, 512>>>(qc, kc, sb, qv, gb, sn);
    scan_phase2<<<Bn * Hn * 4, 256>>>(qv, gb, sn, vc, ovb);

    // norm + gate
    normgate<<<(Bn * Tn * Hn * 32 + 255) / 256, 256>>>(ovb, gp, gw, of);

    // output projection
    sgemm128<<<dim3(1024 / 128, Mr / 128), 256>>>(of, Wo, out, Mr, 1024, 1024);
}

// round 4
// speedup vs baseline: 2.5340x; 2.5340x over previous
#include <cuda_runtime.h>
#include <math.h>

#define Bn 4
#define Tn 2048
#define Dn 1024
#define Hn 4
#define Mn 64
#define NCH 32      // chunks
#define CS 64       // chunk size

// ---------------- scratch (static __device__ globals) ----------------------
__device__ float bufQP[Bn*Tn*512];
__device__ float bufKP[Bn*Tn*512];
__device__ float bufVP[Bn*Tn*1024];
__device__ float bufQC[Bn*Tn*512];
__device__ float bufKC[Bn*Tn*512];
__device__ float bufVC[Bn*Tn*1024];
__device__ float bufS [Bn*Tn*256];
__device__ float bufGP[Bn*Tn*1024];
__device__ float bufE [16*Tn*64];      // E = exp(clip(s)), [bh][t][m]
__device__ float bufQD[16*Tn*64];      // qd = softmax(ok)/D, [bh][t][m]
__device__ float bufOV[Bn*Tn*1024];
__device__ float bufOF[Bn*Tn*1024];
__device__ float bufCK [16*NCH*128*64];  // per-chunk k^T @ E
__device__ float bufHkS[16*NCH*128*64];  // exclusive prefix
__device__ float bufCV [16*NCH*64*256];  // per-chunk E^T @ v
__device__ float bufHvS[16*NCH*64*256];
__device__ float bufSS [16*NCH*64];      // per-chunk column sums of E
__device__ float bufSSP[16*NCH*64];      // exclusive prefix

// ---------------- SGEMM (unchanged) ----------------------------------------
__global__ void __launch_bounds__(256) sgemm128(
    const float* __restrict__ A, const float* __restrict__ B,
    float* __restrict__ C, int Mr, int Nr, int Kr)
{
    __shared__ __align__(16) float As[16][132];
    __shared__ __align__(16) float Bs[16][132];
    int tid = threadIdx.x;
    int tx = tid & 15, ty = tid >> 4;
    int row0 = blockIdx.y * 128, col0 = blockIdx.x * 128;
    float acc[8][8];
#pragma unroll
    for (int i = 0; i < 8; i++)
#pragma unroll
        for (int j = 0; j < 8; j++) acc[i][j] = 0.f;

    const float* Aptr = A + (long)row0 * Kr;
    for (int k0 = 0; k0 < Kr; k0 += 16) {
#pragma unroll
        for (int l = 0; l < 8; l++) {
            int lid = tid + l * 256;
            int r = lid >> 4, cc = lid & 15;
            As[cc][r] = Aptr[(long)r * Kr + k0 + cc];
        }
#pragma unroll
        for (int l = 0; l < 8; l++) {
            int lid = tid + l * 256;
            int r = lid >> 7, cc = lid & 127;
            Bs[r][cc] = B[(long)(k0 + r) * Nr + col0 + cc];
        }
        __syncthreads();
#pragma unroll
        for (int kk = 0; kk < 16; kk++) {
            float a[8], b[8];
            *(float4*)&a[0] = *(const float4*)&As[kk][ty * 8];
            *(float4*)&a[4] = *(const float4*)&As[kk][ty * 8 + 4];
            *(float4*)&b[0] = *(const float4*)&Bs[kk][tx * 8];
            *(float4*)&b[4] = *(const float4*)&Bs[kk][tx * 8 + 4];
#pragma unroll
            for (int i = 0; i < 8; i++)
#pragma unroll
                for (int j = 0; j < 8; j++)
                    acc[i][j] = fmaf(a[i], b[j], acc[i][j]);
        }
        __syncthreads();
    }
#pragma unroll
    for (int i = 0; i < 8; i++) {
        long r = row0 + ty * 8 + i;
#pragma unroll
        for (int j = 0; j < 8; j++)
            C[r * Nr + col0 + tx * 8 + j] = acc[i][j];
    }
}

// ---------------- conv + silu (unchanged) ----------------------------------
__global__ void conv_silu(const float* __restrict__ x, const float* __restrict__ w,
                          float* __restrict__ y, int C)
{
    long idx = (long)blockIdx.x * blockDim.x + threadIdx.x;
    long total = (long)Bn * Tn * C;
    if (idx >= total) return;
    int cidx = idx % C;
    long bt = idx / C;
    int tt = (int)(bt % Tn);
    long bb = bt / Tn;
    float acc = 0.f;
#pragma unroll
    for (int j = 0; j < 4; j++) {
        int ts = tt - 3 + j;
        if (ts >= 0)
            acc = fmaf(x[(bb * Tn + ts) * C + cidx], w[cidx * 4 + j], acc);
    }
    y[idx] = acc / (1.f + expf(-acc));
}

// ---------------- RoPE (unchanged) ----------------------------------------
__global__ void rope_kernel(float* __restrict__ q, float* __restrict__ k)
{
    long idx = (long)blockIdx.x * blockDim.x + threadIdx.x;
    long total = (long)Bn * Tn * 512 / 2;
    if (idx >= total) return;
    int j = idx & 63;
    long rest = idx >> 6;
    int hh = (int)(rest & 3);
    long bt = rest >> 2;
    int tt = (int)(bt % Tn);
    long base = bt * 512 + hh * 128;
    float inv = expf(-(float)(2 * j) * (9.210340371976184f / 128.0f));
    float fr = (float)tt * inv;
    float cs = cosf(fr), sn = sinf(fr);
    float q1 = q[base + j], q2 = q[base + j + 64];
    float k1 = k[base + j], k2 = k[base + j + 64];
    q[base + j]      = q1 * cs - q2 * sn;
    q[base + j + 64] = q2 * cs + q1 * sn;
    k[base + j]      = k1 * cs - k2 * sn;
    k[base + j + 64] = k2 * cs + k1 * sn;
}

// ---------------- E = exp(clip(s)) + per-chunk column sums -----------------
__global__ void __launch_bounds__(256) e_kernel(
    const float* __restrict__ sraw, float* __restrict__ Eb, float* __restrict__ SS)
{
    int blk = blockIdx.x;
    int n = blk & (NCH - 1), bh = blk >> 5;
    int b = bh >> 2, h = bh & 3;
    int tid = threadIdx.x;
    int m = tid & 63, tq = tid >> 6;
    int t0 = n * CS;
    __shared__ float red[4][64];
    float psum = 0.f;
#pragma unroll
    for (int r = 0; r < 16; r++) {
        int t = t0 + r * 4 + tq;
        float sv = sraw[((long)b * Tn + t) * 256 + h * 64 + m];
        sv = fminf(32.f, fmaxf(-32.f, sv));
        float ev = expf(sv);
        Eb[((long)bh * Tn + t) * 64 + m] = ev;
        psum += ev;
    }
    red[tq][m] = psum;
    __syncthreads();
    if (tid < 64)
        SS[(long)blk * 64 + tid] = red[0][tid] + red[1][tid] + red[2][tid] + red[3][tid];
}

// ---------------- contrib_k: CK[bh,n] = k_chunk^T @ E_chunk (128x64) -------
__global__ void __launch_bounds__(256) ck_kernel(
    const float* __restrict__ kc, const float* __restrict__ Eb,
    float* __restrict__ CK)
{
    extern __shared__ float sm[];
    float* ks = sm;            // [64][128]
    float* Es = sm + 64 * 128; // [64][64]
    int blk = blockIdx.x;
    int n = blk & (NCH - 1), bh = blk >> 5;
    int b = bh >> 2, h = bh & 3;
    int t0 = n * CS, tid = threadIdx.x;
    for (int i = tid; i < 64 * 128; i += 256) {
        int t = i >> 7, c = i & 127;
        ks[i] = kc[((long)b * Tn + t0 + t) * 512 + h * 128 + c];
    }
    for (int i = tid; i < 64 * 64; i += 256)
        Es[i] = Eb[((long)bh * Tn + t0) * 64 + i];
    __syncthreads();
    int m = tid & 63, kgrp = tid >> 6;   // 4 groups of 32 k
    float acc[32];
#pragma unroll
    for (int j = 0; j < 32; j++) acc[j] = 0.f;
    for (int t = 0; t < 64; t++) {
        float ev = Es[t * 64 + m];
#pragma unroll
        for (int j = 0; j < 32; j++)
            acc[j] = fmaf(ks[t * 128 + kgrp * 32 + j], ev, acc[j]);
    }
    float* out = CK + (long)blk * 8192;
#pragma unroll
    for (int j = 0; j < 32; j++)
        out[(kgrp * 32 + j) * 64 + m] = acc[j];
}

// ---------------- contrib_v: CV[bh,n] = E_chunk^T @ v_chunk (64x256) -------
__global__ void __launch_bounds__(256) cv_kernel(
    const float* __restrict__ vc, const float* __restrict__ Eb,
    float* __restrict__ CV)
{
    extern __shared__ float sm[];
    float* Es = sm;            // [64][64]
    float* vs = sm + 64 * 64;  // [64][256]
    int blk = blockIdx.x;
    int n = blk & (NCH - 1), bh = blk >> 5;
    int b = bh >> 2, h = bh & 3;
    int t0 = n * CS, tid = threadIdx.x;
    for (int i = tid; i < 64 * 64; i += 256)
        Es[i] = Eb[((long)bh * Tn + t0) * 64 + i];
    for (int i = tid; i < 64 * 256; i += 256) {
        int t = i >> 8, c = i & 255;
        vs[i] = vc[((long)b * Tn + t0 + t) * 1024 + h * 256 + c];
    }
    __syncthreads();
    int v2 = tid & 127, mgrp = tid >> 7;  // 2 groups of 32 m, 2 v's each
    float accx[32], accy[32];
#pragma unroll
    for (int j = 0; j < 32; j++) { accx[j] = 0.f; accy[j] = 0.f; }
    for (int t = 0; t < 64; t++) {
        float2 vv = *(const float2*)&vs[t * 256 + v2 * 2];
#pragma unroll
        for (int j = 0; j < 32; j++) {
            float ev = Es[t * 64 + mgrp * 32 + j];
            accx[j] = fmaf(ev, vv.x, accx[j]);
            accy[j] = fmaf(ev, vv.y, accy[j]);
        }
    }
    float* out = CV + (long)blk * 16384;
#pragma unroll
    for (int j = 0; j < 32; j++) {
        float2 o; o.x = accx[j]; o.y = accy[j];
        *(float2*)&out[(mgrp * 32 + j) * 256 + v2 * 2] = o;
    }
}

// ---------------- exclusive prefix over chunks -----------------------------
__global__ void prefix_kernel(
    const float* __restrict__ CK, float* __restrict__ HkS,
    const float* __restrict__ CV, float* __restrict__ HvS,
    const float* __restrict__ SS, float* __restrict__ SSP)
{
    int e = blockIdx.x * blockDim.x + threadIdx.x;
    int bh = blockIdx.y;
    if (e < 8192) {
        long base = (long)bh * NCH * 8192 + e;
        float run = 0.f;
        for (int n = 0; n < NCH; n++) {
            HkS[base + (long)n * 8192] = run;
            run += CK[base + (long)n * 8192];
        }
    } else if (e < 24576) {
        long base = (long)bh * NCH * 16384 + (e - 8192);
        float run = 0.f;
        for (int n = 0; n < NCH; n++) {
            HvS[base + (long)n * 16384] = run;
            run += CV[base + (long)n * 16384];
        }
    } else if (e < 24640) {
        long base = (long)bh * NCH * 64 + (e - 24576);
        float run = 0.f;
        for (int n = 0; n < NCH; n++) {
            SSP[base + n * 64] = run;
            run += SS[base + n * 64];
        }
    }
}

// ---------------- stage 1: ok -> softmax -> qd -----------------------------
__global__ void __launch_bounds__(256) stage1_kernel(
    const float* __restrict__ qc, const float* __restrict__ kc,
    const float* __restrict__ Eb, const float* __restrict__ HkS,
    const float* __restrict__ SSP, float* __restrict__ qd)
{
    extern __shared__ float sm[];
    float* qs  = sm;                     // [64][129]
    float* uni = sm + 64 * 129;          // ks [64][129] then hks [128][64]
    float* Es  = uni + 64 * 129;         // [64][64]
    float* QK  = Es + 64 * 64;           // [64][65]
    float* Dc  = QK + 64 * 65;           // [64][65]
    int blk = blockIdx.x;
    int n = blk & (NCH - 1), bh = blk >> 5;
    int b = bh >> 2, h = bh & 3;
    int t0 = n * CS, tid = threadIdx.x;
    const float scale = 0.08838834764831845f;  // 1/sqrt(128)

    for (int i = tid; i < 64 * 128; i += 256) {
        int t = i >> 7, c = i & 127;
        long g = ((long)b * Tn + t0 + t) * 512 + h * 128 + c;
        qs[t * 129 + c]  = qc[g] * scale;
        uni[t * 129 + c] = kc[g];
    }
    for (int i = tid; i < 64 * 64; i += 256)
        Es[i] = Eb[((long)bh * Tn + t0) * 64 + i];
    __syncthreads();

    // QK (causal) + Dc cumsum
    {
        int t = tid >> 2, sgrp = tid & 3;
        float acc[16];
#pragma unroll
        for (int j = 0; j < 16; j++) acc[j] = 0.f;
        for (int k = 0; k < 128; k++) {
            float qv_ = qs[t * 129 + k];
#pragma unroll
            for (int j = 0; j < 16; j++)
                acc[j] = fmaf(qv_, uni[(sgrp * 16 + j) * 129 + k], acc[j]);
        }
#pragma unroll
        for (int j = 0; j < 16; j++) {
            int s = sgrp * 16 + j;
            QK[t * 65 + s] = (s <= t) ? acc[j] : 0.f;
        }
    }
    if (tid < 64) {
        float run = SSP[(long)blk * 64 + tid];
        for (int t = 0; t < 64; t++) {
            run += Es[t * 64 + tid];
            Dc[t * 65 + tid] = run;
        }
    }
    __syncthreads();

    // overwrite ks region with hks [128][64]
    for (int i = tid; i < 128 * 64; i += 256)
        uni[i] = HkS[(long)blk * 8192 + i];
    __syncthreads();

    // ok = QK@E + q@Hk, normalize, softmax, qd
    {
        int t = tid >> 2, mgrp = tid & 3;
        float acc[16];
#pragma unroll
        for (int j = 0; j < 16; j++) acc[j] = 0.f;
        for (int s = 0; s < 64; s++) {
            float w = QK[t * 65 + s];
#pragma unroll
            for (int j = 0; j < 16; j++)
                acc[j] = fmaf(w, Es[s * 64 + mgrp * 16 + j], acc[j]);
        }
        for (int k = 0; k < 128; k++) {
            float qv_ = qs[t * 129 + k];
#pragma unroll
            for (int j = 0; j < 16; j++)
                acc[j] = fmaf(qv_, uni[k * 64 + mgrp * 16 + j], acc[j]);
        }
        float dinv[16];
        float mx = -INFINITY;
#pragma unroll
        for (int j = 0; j < 16; j++) {
            dinv[j] = 1.f / Dc[t * 65 + mgrp * 16 + j];
            acc[j] *= dinv[j];
            mx = fmaxf(mx, acc[j]);
        }
        mx = fmaxf(mx, __shfl_xor_sync(0xffffffffu, mx, 1));
        mx = fmaxf(mx, __shfl_xor_sync(0xffffffffu, mx, 2));
        float sum = 0.f;
#pragma unroll
        for (int j = 0; j < 16; j++) {
            acc[j] = expf(acc[j] - mx);
            sum += acc[j];
        }
        sum += __shfl_xor_sync(0xffffffffu, sum, 1);
        sum += __shfl_xor_sync(0xffffffffu, sum, 2);
        float invs = 1.f / sum;
        long base = ((long)bh * Tn + t0 + t) * 64 + mgrp * 16;
#pragma unroll
        for (int j = 0; j < 16; j++)
            qd[base + j] = acc[j] * invs * dinv[j];
    }
}

// ---------------- stage 2: ov = (qd@E^T masked)@v + qd@Hv ------------------
__global__ void __launch_bounds__(256) stage2_kernel(
    const float* __restrict__ qd, const float* __restrict__ Eb,
    const float* __restrict__ vc, const float* __restrict__ HvS,
    float* __restrict__ ov)
{
    extern __shared__ float sm[];
    float* qds = sm;                 // [64][65]
    float* Es  = qds + 64 * 65;      // [64][65]
    float* W   = Es + 64 * 65;       // [64][65]
    float* vs  = W + 64 * 65;        // [64][256]
    float* hvs = vs + 64 * 256;      // [64][256]
    int blk = blockIdx.x;
    int n = blk & (NCH - 1), bh = blk >> 5;
    int b = bh >> 2, h = bh & 3;
    int t0 = n * CS, tid = threadIdx.x;

    for (int i = tid; i < 64 * 64; i += 256) {
        int t = i >> 6, m = i & 63;
        long base = ((long)bh * Tn + t0) * 64 + i;
        qds[t * 65 + m] = qd[base];
        Es[t * 65 + m]  = Eb[base];
    }
    for (int i = tid; i < 64 * 256; i += 256) {
        int t = i >> 8, c = i & 255;
        vs[i]  = vc[((long)b * Tn + t0 + t) * 1024 + h * 256 + c];
        hvs[i] = HvS[(long)blk * 16384 + i];
    }
    __syncthreads();

    // W[t][s] = sum_m qd[t][m]*E[s][m], causal
    {
        int t = tid >> 2, sgrp = tid & 3;
        float acc[16];
#pragma unroll
        for (int j = 0; j < 16; j++) acc[j] = 0.f;
        for (int m = 0; m < 64; m++) {
            float qv_ = qds[t * 65 + m];
#pragma unroll
            for (int j = 0; j < 16; j++)
                acc[j] = fmaf(qv_, Es[(sgrp * 16 + j) * 65 + m], acc[j]);
        }
#pragma unroll
        for (int j = 0; j < 16; j++) {
            int s = sgrp * 16 + j;
            W[t * 65 + s] = (s <= t) ? acc[j] : 0.f;
        }
    }
    __syncthreads();

    // ov[t][v] = sum_s W[t][s]*v[s][v] + sum_m qd[t][m]*Hv[m][v]
    {
        int t = tid >> 2, vgrp = tid & 3;
        float acc[64];
#pragma unroll
        for (int j = 0; j < 64; j++) acc[j] = 0.f;
        for (int s = 0; s < 64; s++) {
            float w = W[t * 65 + s];
#pragma unroll
            for (int j = 0; j < 64; j++)
                acc[j] = fmaf(w, vs[s * 256 + vgrp * 64 + j], acc[j]);
        }
        for (int m = 0; m < 64; m++) {
            float qv_ = qds[t * 65 + m];
#pragma unroll
            for (int j = 0; j < 64; j++)
                acc[j] = fmaf(qv_, hvs[m * 256 + vgrp * 64 + j], acc[j]);
        }
        long base = ((long)b * Tn + t0 + t) * 1024 + h * 256 + vgrp * 64;
#pragma unroll
        for (int j = 0; j < 16; j++)
            *(float4*)&ov[base + j * 4] = *(float4*)&acc[j * 4];
    }
}

// ---------------- norm + gate (unchanged) ----------------------------------
__global__ void normgate(const float* __restrict__ ovb, const float* __restrict__ gp,
                         const float* __restrict__ gw, float* __restrict__ out)
{
    int warp = (int)(((long)blockIdx.x * blockDim.x + threadIdx.x) >> 5);
    int lane = threadIdx.x & 31;
    if (warp >= Bn * Tn * Hn) return;
    long base = (long)warp * 256;
    float vals[8];
    float ss = 0.f;
#pragma unroll
    for (int i = 0; i < 8; i++) {
        float v = ovb[base + lane + i * 32];
        vals[i] = v;
        ss = fmaf(v, v, ss);
    }
#pragma unroll
    for (int off = 16; off; off >>= 1)
        ss += __shfl_xor_sync(0xffffffffu, ss, off);
    float scale = rsqrtf(ss * (1.f / 256.f) + 1e-5f);
#pragma unroll
    for (int i = 0; i < 8; i++) {
        int j = lane + i * 32;
        float gv = gp[base + j];
        float sil = gv / (1.f + expf(-gv));
        out[base + j] = vals[i] * scale * gw[j] * sil;
    }
}

// ---------------- host launch ----------------------------------------------
extern "C" void kernel_launch(void* const* d_in, const int* in_sizes, int n_in,
                              void* d_out, int out_size)
{
    const float* X  = (const float*)d_in[0];
    const float* Wq = (const float*)d_in[1];
    const float* Wk = (const float*)d_in[2];
    const float* Wv = (const float*)d_in[3];
    const float* Ws = (const float*)d_in[4];
    const float* Wg = (const float*)d_in[5];
    const float* Wo = (const float*)d_in[6];
    const float* qw = (const float*)d_in[7];
    const float* kw = (const float*)d_in[8];
    const float* vw = (const float*)d_in[9];
    const float* gw = (const float*)d_in[10];
    float* out = (float*)d_out;

    float *qp, *kp, *vp, *qc, *kc, *vc, *sb, *gp, *Eb, *qdb, *ovb, *of;
    float *ck, *hks, *cv, *hvs, *ssb, *ssp;
    cudaGetSymbolAddress((void**)&qp, bufQP);
    cudaGetSymbolAddress((void**)&kp, bufKP);
    cudaGetSymbolAddress((void**)&vp, bufVP);
    cudaGetSymbolAddress((void**)&qc, bufQC);
    cudaGetSymbolAddress((void**)&kc, bufKC);
    cudaGetSymbolAddress((void**)&vc, bufVC);
    cudaGetSymbolAddress((void**)&sb, bufS);
    cudaGetSymbolAddress((void**)&gp, bufGP);
    cudaGetSymbolAddress((void**)&Eb, bufE);
    cudaGetSymbolAddress((void**)&qdb, bufQD);
    cudaGetSymbolAddress((void**)&ovb, bufOV);
    cudaGetSymbolAddress((void**)&of, bufOF);
    cudaGetSymbolAddress((void**)&ck, bufCK);
    cudaGetSymbolAddress((void**)&hks, bufHkS);
    cudaGetSymbolAddress((void**)&cv, bufCV);
    cudaGetSymbolAddress((void**)&hvs, bufHvS);
    cudaGetSymbolAddress((void**)&ssb, bufSS);
    cudaGetSymbolAddress((void**)&ssp, bufSSP);

    const int SM_CK = (64 * 128 + 64 * 64) * 4;
    const int SM_CV = (64 * 64 + 64 * 256) * 4;
    const int SM_S1 = (64 * 129 * 2 + 64 * 64 + 64 * 65 * 2) * 4;
    const int SM_S2 = (64 * 65 * 3 + 64 * 256 * 2) * 4;
    cudaFuncSetAttribute(ck_kernel,     cudaFuncAttributeMaxDynamicSharedMemorySize, SM_CK);
    cudaFuncSetAttribute(cv_kernel,     cudaFuncAttributeMaxDynamicSharedMemorySize, SM_CV);
    cudaFuncSetAttribute(stage1_kernel, cudaFuncAttributeMaxDynamicSharedMemorySize, SM_S1);
    cudaFuncSetAttribute(stage2_kernel, cudaFuncAttributeMaxDynamicSharedMemorySize, SM_S2);

    const int Mr = Bn * Tn;  // 8192

    sgemm128<<<dim3(512 / 128, Mr / 128), 256>>>(X, Wq, qp, Mr, 512, 1024);
    sgemm128<<<dim3(512 / 128, Mr / 128), 256>>>(X, Wk, kp, Mr, 512, 1024);
    sgemm128<<<dim3(1024 / 128, Mr / 128), 256>>>(X, Wv, vp, Mr, 1024, 1024);
    sgemm128<<<dim3(256 / 128, Mr / 128), 256>>>(X, Ws, sb, Mr, 256, 1024);
    sgemm128<<<dim3(1024 / 128, Mr / 128), 256>>>(X, Wg, gp, Mr, 1024, 1024);

    conv_silu<<<(Bn * Tn * 512 + 255) / 256, 256>>>(qp, qw, qc, 512);
    conv_silu<<<(Bn * Tn * 512 + 255) / 256, 256>>>(kp, kw, kc, 512);
    conv_silu<<<(Bn * Tn * 1024 + 255) / 256, 256>>>(vp, vw, vc, 1024);
    rope_kernel<<<(Bn * Tn * 512 / 2 + 255) / 256, 256>>>(qc, kc);

    // chunked ABC
    e_kernel<<<16 * NCH, 256>>>(sb, Eb, ssb);
    ck_kernel<<<16 * NCH, 256, SM_CK>>>(kc, Eb, ck);
    cv_kernel<<<16 * NCH, 256, SM_CV>>>(vc, Eb, cv);
    prefix_kernel<<<dim3(97, 16), 256>>>(ck, hks, cv, hvs, ssb, ssp);
    stage1_kernel<<<16 * NCH, 256, SM_S1>>>(qc, kc, Eb, hks, ssp, qdb);
    stage2_kernel<<<16 * NCH, 256, SM_S2>>>(qdb, Eb, vc, hvs, ovb);

    normgate<<<(Bn * Tn * Hn * 32 + 255) / 256, 256>>>(ovb, gp, gw, of);
    sgemm128<<<dim3(1024 / 128, Mr / 128), 256>>>(of, Wo, out, Mr, 1024, 1024);
}